// round 16
// baseline (speedup 1.0000x reference)
#include <cuda_runtime.h>
#include <cuda_fp16.h>
#include <cstdint>

#define HSTEP (1.0f/63.0f)
#define CH_STEPS 7
#define CH_ROWS  1792

// ---------------- scratch ----------------
static __device__ float g_y[128*64*232];
static __device__ float g_dknot[63*232*128];
static __device__ float g_dmid [63*232*128];
static __device__ float g_z[128*256];
// precompute path (fp16 3-segment split)
static __device__ __half g_Asp[(size_t)16128*704];   // [Dh|Dh|Dl]
static __device__ __half g_Bsp[(size_t)65536*704];   // [Bh|Bl|Bh]
static __device__ float g_Dp [(size_t)16128*256];
static __device__ float g_bt [(size_t)16128*256];
static __device__ float g_fb4T[256*256];
static __device__ float g_zero[256];
static __device__ float g_C[(size_t)CH_ROWS*65536];  // 470 MB ring chunk

// ---------------- helpers ----------------
__device__ __forceinline__ float2 ffma2(float2 a, float2 b, float2 c){
    unsigned long long au, bu, cu, du;
    au = *reinterpret_cast<unsigned long long*>(&a);
    bu = *reinterpret_cast<unsigned long long*>(&b);
    cu = *reinterpret_cast<unsigned long long*>(&c);
    asm("fma.rn.f32x2 %0,%1,%2,%3;" : "=l"(du) : "l"(au), "l"(bu), "l"(cu));
    return *reinterpret_cast<float2*>(&du);
}

__device__ __forceinline__ uint32_t smem_u32(const void* p){
    uint32_t a;
    asm("{ .reg .u64 t; cvta.to.shared.u64 t, %1; cvt.u32.u64 %0, t; }"
        : "=r"(a) : "l"(p));
    return a;
}

__device__ __forceinline__ void ldsm4(uint32_t* r, uint32_t addr){
    asm volatile("ldmatrix.sync.aligned.m8n8.x4.shared.b16 {%0,%1,%2,%3}, [%4];"
        : "=r"(r[0]), "=r"(r[1]), "=r"(r[2]), "=r"(r[3]) : "r"(addr));
}

__device__ __forceinline__ void mma_f16(float* c, const uint32_t* a, const uint32_t* b){
    asm volatile("mma.sync.aligned.m16n8k16.row.col.f32.f16.f16.f32 "
        "{%0,%1,%2,%3}, {%4,%5,%6,%7}, {%8,%9}, {%0,%1,%2,%3};"
        : "+f"(c[0]), "+f"(c[1]), "+f"(c[2]), "+f"(c[3])
        : "r"(a[0]), "r"(a[1]), "r"(a[2]), "r"(a[3]), "r"(b[0]), "r"(b[1]));
}

__device__ __forceinline__ void cpasync16(uint32_t dst, const void* src){
    asm volatile("cp.async.cg.shared.global [%0], [%1], 16;" :: "r"(dst), "l"(src));
}

__device__ __forceinline__ void block_reduce_sum4(float& s0, float& q0,
                                                  float& s1, float& q1){
    __shared__ float sh[128];
    const unsigned m = 0xffffffffu;
    #pragma unroll
    for (int off = 16; off; off >>= 1){
        s0 += __shfl_down_sync(m, s0, off);
        q0 += __shfl_down_sync(m, q0, off);
        s1 += __shfl_down_sync(m, s1, off);
        q1 += __shfl_down_sync(m, q1, off);
    }
    int w = threadIdx.x >> 5, l = threadIdx.x & 31;
    if (l == 0){ sh[w] = s0; sh[32+w] = q0; sh[64+w] = s1; sh[96+w] = q1; }
    __syncthreads();
    if (threadIdx.x == 0){
        float a = 0.f, bq = 0.f, c = 0.f, d = 0.f;
        int nw = blockDim.x >> 5;
        for (int i = 0; i < nw; i++){
            a += sh[i]; bq += sh[32+i]; c += sh[64+i]; d += sh[96+i];
        }
        sh[0] = a; sh[32] = bq; sh[64] = c; sh[96] = d;
    }
    __syncthreads();
    s0 = sh[0]; q0 = sh[32]; s1 = sh[64]; q1 = sh[96];
}

// ---- 1) fused: depth-2 log-signature + sig_norm LN + control y ----
__global__ void k_sig(const float* __restrict__ x,
                      const float* __restrict__ sg, const float* __restrict__ sb){
    extern __shared__ float ls[];          // 64 x 232 floats
    __shared__ float psh[64*21];
    int b = blockIdx.x, t = threadIdx.x;
    for (int idx = t; idx < 64*21; idx += 256){
        int n = idx / 21, i = idx % 21;
        psh[idx] = (i == 0) ? (float)n * HSTEP : x[(b*64 + n)*20 + (i-1)];
    }
    __syncthreads();
    int ch = t;
    if (ch < 21){
        for (int n = 0; n < 64; n++) ls[n*232 + ch] = psh[n*21 + ch];
    } else if (ch < 231){
        int pp = ch - 21, i = 0, rem = pp;
        while (rem >= 20 - i){ rem -= 20 - i; i++; }
        int j = i + 1 + rem;
        float acc = 0.f, pip = 0.f, pjp = 0.f;
        for (int n = 0; n < 64; n++){
            float pi = psh[n*21 + i], pj = psh[n*21 + j];
            acc += 0.5f*(pip*(pj - pjp) - (pi - pip)*pjp);
            ls[n*232 + ch] = acc;
            pip = pi; pjp = pj;
        }
    }
    __syncthreads();
    int w = t >> 5, l = t & 31;
    const unsigned fm = 0xffffffffu;
    for (int n = w; n < 64; n += 8){
        float s = 0.f, q = 0.f;
        for (int c = l; c < 231; c += 32){
            float v = ls[n*232 + c]; s += v; q += v*v;
        }
        #pragma unroll
        for (int off = 16; off; off >>= 1){
            s += __shfl_down_sync(fm, s, off);
            q += __shfl_down_sync(fm, q, off);
        }
        s = __shfl_sync(fm, s, 0); q = __shfl_sync(fm, q, 0);
        float mean = s*(1.0f/231.0f);
        float var  = q*(1.0f/231.0f) - mean*mean;
        float rstd = rsqrtf(var + 1e-5f);
        size_t ro = ((size_t)b*64 + n)*232;
        for (int c = l; c < 231; c += 32)
            g_y[ro + 1 + c] = (ls[n*232 + c] - mean)*rstd*sg[c] + sb[c];
        if (l == 0) g_y[ro] = (float)n * HSTEP;
    }
}

// ---- 2) natural cubic spline derivatives ----
__global__ void k_spline(){
    __shared__ float cpS[64], idS[64];
    int t = threadIdx.x;
    if (t == 0){
        double ad = (1.0/63.0)/6.0, bd = 2.0*(1.0/63.0)/3.0, cprev = 0.0;
        for (int i = 1; i <= 62; i++){
            double den = bd - ad*cprev, cp = ad/den;
            cpS[i] = (float)cp; idS[i] = (float)(1.0/den); cprev = cp;
        }
    }
    __syncthreads();
    int g = blockIdx.x*128 + t;
    int b = g / 232, c = g % 232;
    float yv[64], M[64];
    for (int n = 0; n < 64; n++) yv[n] = g_y[((size_t)b*64 + n)*232 + c];
    const float ad = HSTEP/6.0f;
    M[0] = 0.f; M[63] = 0.f;
    float prev = 0.f;
    for (int i = 1; i <= 62; i++){
        float rhs = (yv[i+1] - 2.f*yv[i] + yv[i-1]) * 63.0f;
        prev = (rhs - ad*prev) * idS[i];
        M[i] = prev;
    }
    for (int i = 61; i >= 1; i--) M[i] -= cpS[i]*M[i+1];
    for (int n = 0; n < 63; n++){
        float dy = (yv[n+1] - yv[n]) * 63.0f;
        size_t o = ((size_t)n*232 + c)*128 + b;
        g_dknot[o] = dy - (HSTEP/6.0f) *(2.f*M[n] + M[n+1]);
        g_dmid [o] = dy + (HSTEP/24.0f)*(M[n] - M[n+1]);
    }
}

// ---- 3) merged pack: fp16 hi/lo split of fW4 and D ----
__global__ void k_pack(const float* __restrict__ fW4){
    int blk = blockIdx.x, c = threadIdx.x;
    if (blk < 65536){
        if (c < 232){
            float v = fW4[(size_t)blk*232 + c];
            __half h = __float2half(v);
            __half l = __float2half(v - __half2float(h));
            g_Bsp[(size_t)blk*704 + c]       = h;
            g_Bsp[(size_t)blk*704 + 232 + c] = l;
            g_Bsp[(size_t)blk*704 + 464 + c] = h;
        } else if (c < 240){
            g_Bsp[(size_t)blk*704 + 696 + (c - 232)] = __float2half(0.f);
        }
    } else {
        int j = blk - 65536;
        int n = j >> 8, e = (j >> 7) & 1, b = j & 127;
        const float* src = e ? g_dmid : g_dknot;
        if (c < 232){
            float v = src[((size_t)n*232 + c)*128 + b];
            __half h = __float2half(v);
            __half l = __float2half(v - __half2float(h));
            g_Asp[(size_t)j*704 + c]       = h;
            g_Asp[(size_t)j*704 + 232 + c] = h;
            g_Asp[(size_t)j*704 + 464 + c] = l;
            g_Dp[(size_t)j*256 + c] = v;
        } else {
            if (c < 240) g_Asp[(size_t)j*704 + 696 + (c - 232)] = __float2half(0.f);
            g_Dp[(size_t)j*256 + c] = 0.f;
        }
    }
}

__global__ void k_packfbT(const float* __restrict__ fb4){
    int c = blockIdx.x, h = threadIdx.x;
    g_fb4T[c*256 + h] = (c < 232) ? fb4[(size_t)h*232 + c] : 0.f;
}

// ---- 4) initial hidden state ----
__global__ void k_h0(const float* __restrict__ x,  const float* __restrict__ hW1,
                     const float* __restrict__ hb1, const float* __restrict__ hW2,
                     const float* __restrict__ hb2){
    int b = blockIdx.x, t = threadIdx.x;
    __shared__ float x0[20];
    __shared__ float hid[256];
    if (t < 20) x0[t] = x[(size_t)b*64*20 + t];
    __syncthreads();
    float s = hb1[t];
    for (int d = 0; d < 20; d++) s = fmaf(x0[d], hW1[d*256 + t], s);
    hid[t] = fmaxf(s, 0.f);
    __syncthreads();
    float s2 = hb2[t];
    for (int k = 0; k < 256; k++) s2 = fmaf(hid[k], hW2[k*256 + t], s2);
    g_z[b*256 + t] = s2;
}

// ---- generic tiled GEMM (bias-term precompute only) ----
__global__ void __launch_bounds__(256) k_gemm(
    const float* __restrict__ in, const float* __restrict__ W,
    const float* __restrict__ bias, float* __restrict__ out,
    int K, int Nout)
{
    __shared__ float wsh[2048];
    __shared__ float ish[512];
    int n0 = blockIdx.x*64, b0 = blockIdx.y*16;
    int t = threadIdx.x, bi = t >> 4, ng = t & 15;
    float4 bia = *(const float4*)(bias + n0 + ng*4);
    float2 acc0 = make_float2(bia.x, bia.y);
    float2 acc1 = make_float2(bia.z, bia.w);
    for (int k0 = 0; k0 < K; k0 += 32){
        __syncthreads();
        #pragma unroll
        for (int j = 0; j < 8; j++){
            int e = t + j*256;
            wsh[e] = W[(size_t)(k0 + (e >> 6))*Nout + n0 + (e & 63)];
        }
        #pragma unroll
        for (int j = 0; j < 2; j++){
            int e = t + j*256;
            ish[e] = in[(size_t)(b0 + (e >> 5))*K + k0 + (e & 31)];
        }
        __syncthreads();
        #pragma unroll
        for (int kk = 0; kk < 32; kk++){
            float zv = ish[bi*32 + kk];
            float2 zz = make_float2(zv, zv);
            const float2* wp = (const float2*)(wsh + kk*64 + ng*4);
            acc0 = ffma2(zz, wp[0], acc0);
            acc1 = ffma2(zz, wp[1], acc1);
        }
    }
    float4 o = make_float4(acc0.x, acc0.y, acc1.x, acc1.y);
    *(float4*)(out + (size_t)(b0 + bi)*Nout + n0 + ng*4) = o;
}

// ---- big GEMM on fp16 HMMA: C[1792 x 65536] = Asp_chunk @ Bspᵀ, K=704 ----
__global__ void __launch_bounds__(256, 2) k_tc(
    const __half* __restrict__ A, const __half* __restrict__ Bm,
    float* __restrict__ C)
{
    extern __shared__ __align__(128) char dsm[];
    uint32_t base = (smem_u32(dsm) + 127u) & ~127u;
    int t = threadIdx.x, lane = t & 31, warp = t >> 5;
    int mw = warp & 1, nw = warp >> 1;
    size_t j0 = (size_t)blockIdx.x * 128, n0 = (size_t)blockIdx.y * 128;
    const char* Ab = (const char*)A  + j0*1408;
    const char* Bb = (const char*)Bm + n0*1408;

    auto stg = [&](int ck, int s){
        uint32_t sb = base + s*32768u;
        #pragma unroll
        for (int i = 0; i < 4; i++){
            int e = t*4 + i;
            int row = e >> 3, q = e & 7;
            uint32_t d = sb + row*128 + ((q ^ (row & 7)) << 4);
            cpasync16(d, Ab + (size_t)row*1408 + ck*128 + q*16);
        }
        #pragma unroll
        for (int i = 0; i < 4; i++){
            int e = t*4 + i;
            int row = e >> 3, q = e & 7;
            uint32_t d = sb + 16384u + row*128 + ((q ^ (row & 7)) << 4);
            cpasync16(d, Bb + (size_t)row*1408 + ck*128 + q*16);
        }
        asm volatile("cp.async.commit_group;" ::: "memory");
    };

    float acc[4][4][4];
    #pragma unroll
    for (int mi = 0; mi < 4; mi++)
        #pragma unroll
        for (int ni = 0; ni < 4; ni++)
            #pragma unroll
            for (int r = 0; r < 4; r++) acc[mi][ni][r] = 0.f;

    stg(0, 0); stg(1, 1); stg(2, 2);

    for (int ck = 0; ck < 11; ck++){
        if (ck < 8) asm volatile("cp.async.wait_group 2;" ::: "memory");
        else        asm volatile("cp.async.wait_group 0;" ::: "memory");
        __syncthreads();
        uint32_t sA = base + (uint32_t)(ck % 3)*32768u;
        uint32_t sB = sA + 16384u;
        #pragma unroll
        for (int kk = 0; kk < 4; kk++){
            uint32_t afr[4][4], bfr[2][4];
            #pragma unroll
            for (int mi = 0; mi < 4; mi++){
                int row = mw*64 + mi*16 + (lane & 15);
                int q = kk*2 + (lane >> 4);
                ldsm4(afr[mi], sA + row*128 + ((q ^ (row & 7)) << 4));
            }
            #pragma unroll
            for (int nj = 0; nj < 2; nj++){
                int row = nw*32 + nj*16 + (lane & 7) + ((lane >> 4) & 1)*8;
                int q = kk*2 + ((lane >> 3) & 1);
                ldsm4(bfr[nj], sB + row*128 + ((q ^ (row & 7)) << 4));
            }
            #pragma unroll
            for (int mi = 0; mi < 4; mi++)
                #pragma unroll
                for (int ni = 0; ni < 4; ni++)
                    mma_f16(acc[mi][ni], afr[mi], &bfr[ni >> 1][(ni & 1)*2]);
        }
        __syncthreads();
        if (ck + 3 < 11) stg(ck + 3, ck % 3);
    }

    #pragma unroll
    for (int mi = 0; mi < 4; mi++){
        size_t r0 = j0 + mw*64 + mi*16 + (lane >> 2);
        float* row0 = C + r0*65536 + n0 + nw*32 + (lane & 3)*2;
        float* row1 = row0 + (size_t)8*65536;
        #pragma unroll
        for (int ni = 0; ni < 4; ni++){
            *(float2*)(row0 + ni*8) = make_float2(acc[mi][ni][0], acc[mi][ni][1]);
            *(float2*)(row1 + ni*8) = make_float2(acc[mi][ni][2], acc[mi][ni][3]);
        }
    }
}

// ---- persistent scan: 64 blocks x 512 threads, 2 batches per block ----
__global__ void __launch_bounds__(512) k_scan(
    const float* __restrict__ fW1, const float* __restrict__ fb1,
    const float* __restrict__ g1,  const float* __restrict__ be1,
    const float* __restrict__ fW2, const float* __restrict__ fb2,
    const float* __restrict__ g2,  const float* __restrict__ be2,
    const float* __restrict__ fW3, const float* __restrict__ fb3,
    const float* __restrict__ C,   const float* __restrict__ bt,
    float* __restrict__ zg, int jgbase)
{
    int t = threadIdx.x;
    int team = t >> 8, tl = t & 255;
    int bb = blockIdx.x*2;
    __shared__ float zsh[2][256], zmd[2][256];
    __shared__ __align__(16) float a1sh[2][1024];
    __shared__ float a2sh[2][256], a3sh[2][256];
    __shared__ float2 red2[2][2][256];

    zsh[team][tl] = zg[(bb + team)*256 + tl];
    __syncthreads();

    for (int s = 0; s < CH_STEPS; s++){
        #pragma unroll
        for (int e = 0; e < 2; e++){
            const float* zin0 = e ? zmd[0] : zsh[0];
            const float* zin1 = e ? zmd[1] : zsh[1];
            float2 bv = __ldg((const float2*)fb1 + t);
            float2 A0 = bv, A1 = bv;
            #pragma unroll 8
            for (int k = 0; k < 256; k++){
                float2 w = __ldg((const float2*)(fW1 + (size_t)k*1024) + t);
                float z0 = zin0[k], z1 = zin1[k];
                A0 = ffma2(make_float2(z0, z0), w, A0);
                A1 = ffma2(make_float2(z1, z1), w, A1);
            }
            float s0 = A0.x + A0.y, q0 = A0.x*A0.x + A0.y*A0.y;
            float s1 = A1.x + A1.y, q1 = A1.x*A1.x + A1.y*A1.y;
            block_reduce_sum4(s0, q0, s1, q1);
            float m0 = s0*(1.0f/1024.0f), v0 = q0*(1.0f/1024.0f) - m0*m0;
            float m1 = s1*(1.0f/1024.0f), v1 = q1*(1.0f/1024.0f) - m1*m1;
            float r0 = rsqrtf(v0 + 1e-5f), r1 = rsqrtf(v1 + 1e-5f);
            {
                float2 gg = __ldg((const float2*)g1 + t);
                float2 bbv = __ldg((const float2*)be1 + t);
                ((float2*)a1sh[0])[t] = make_float2(
                    fmaxf((A0.x - m0)*r0*gg.x + bbv.x, 0.f),
                    fmaxf((A0.y - m0)*r0*gg.y + bbv.y, 0.f));
                ((float2*)a1sh[1])[t] = make_float2(
                    fmaxf((A1.x - m1)*r1*gg.x + bbv.x, 0.f),
                    fmaxf((A1.y - m1)*r1*gg.y + bbv.y, 0.f));
            }
            __syncthreads();
            {
                float acc0 = 0.f, acc1 = 0.f;
                const float* wb = fW2 + (size_t)team*512*256 + tl;
                const float* x0 = a1sh[0] + team*512;
                const float* x1 = a1sh[1] + team*512;
                #pragma unroll 8
                for (int k = 0; k < 512; k++){
                    float w = __ldg(wb + (size_t)k*256);
                    acc0 = fmaf(x0[k], w, acc0);
                    acc1 = fmaf(x1[k], w, acc1);
                }
                red2[team][0][tl] = make_float2(acc0, 0.f);
                red2[team][1][tl] = make_float2(acc1, 0.f);
            }
            __syncthreads();
            {
                float tot = red2[0][team][tl].x + red2[1][team][tl].x
                          + __ldg(fb2 + tl);
                float sA = (team == 0) ? tot : 0.f;
                float qA = (team == 0) ? tot*tot : 0.f;
                float sB = (team == 1) ? tot : 0.f;
                float qB = (team == 1) ? tot*tot : 0.f;
                block_reduce_sum4(sA, qA, sB, qB);
                float sm = team ? sB : sA, qm = team ? qB : qA;
                float mean = sm*(1.0f/256.0f), var = qm*(1.0f/256.0f) - mean*mean;
                float rstd = rsqrtf(var + 1e-5f);
                a2sh[team][tl] = fmaxf((tot - mean)*rstd*__ldg(g2 + tl)
                                       + __ldg(be2 + tl), 0.f);
            }
            __syncthreads();
            {
                float acc3 = __ldg(fb3 + tl);
                const float* a2p = a2sh[team];
                #pragma unroll 8
                for (int k = 0; k < 256; k++)
                    acc3 = fmaf(a2p[k], __ldg(fW3 + (size_t)k*256 + tl), acc3);
                a3sh[team][tl] = fmaxf(acc3, 0.f);
            }
            __syncthreads();
            {
                int rloc = (2*s + e)*128 + bb + team;
                const float* Crow = C + (size_t)rloc*65536 + tl;
                float g = __ldg(bt + (size_t)(jgbase + rloc)*256 + tl);
                const float* a3p = a3sh[team];
                #pragma unroll 8
                for (int k = 0; k < 256; k++)
                    g = fmaf(a3p[k], __ldg(Crow + (size_t)k*256), g);
                if (e == 0) zmd[team][tl] = zsh[team][tl] + 0.5f*HSTEP*g;
                else        zsh[team][tl] = zsh[team][tl] + HSTEP*g;
            }
            __syncthreads();
        }
    }
    zg[(bb + team)*256 + tl] = zsh[team][tl];
}

// ---- output heads ----
__global__ void k_head(const float* __restrict__ yW1, const float* __restrict__ yb1,
                       const float* __restrict__ yW2, const float* __restrict__ yb2,
                       const float* __restrict__ zW1, const float* __restrict__ zb1,
                       const float* __restrict__ zW2, const float* __restrict__ zb2,
                       float* __restrict__ out){
    int b = blockIdx.x, t = threadIdx.x;
    __shared__ float hsh[256], t1[128], t2[256];
    hsh[t] = g_z[b*256 + t];
    __syncthreads();
    float s = zb1[t];
    for (int k = 0; k < 256; k++) s = fmaf(hsh[k], zW1[k*256 + t], s);
    t2[t] = fmaxf(s, 0.f);
    if (t < 128){
        float s1 = yb1[t];
        for (int k = 0; k < 256; k++) s1 = fmaf(hsh[k], yW1[k*128 + t], s1);
        t1[t] = fmaxf(s1, 0.f);
    }
    __syncthreads();
    if (t == 0){
        float y = yb2[0];
        for (int j = 0; j < 128; j++) y = fmaf(t1[j], yW2[j], y);
        out[b] = y;
    }
    if (t < 20){
        float zz = zb2[t];
        for (int k = 0; k < 256; k++) zz = fmaf(t2[k], zW2[k*20 + t], zz);
        out[128 + b*20 + t] = zz;
    }
    out[128 + 2560 + b*256 + t] = hsh[t];
}

extern "C" void kernel_launch(void* const* d_in, const int* in_sizes, int n_in,
                              void* d_out, int out_size){
    const float* x  =(const float*)d_in[0];
    const float* hW1=(const float*)d_in[1]; const float* hb1=(const float*)d_in[2];
    const float* hW2=(const float*)d_in[3]; const float* hb2=(const float*)d_in[4];
    const float* fW1=(const float*)d_in[5]; const float* fb1=(const float*)d_in[6];
    const float* g1 =(const float*)d_in[7]; const float* be1=(const float*)d_in[8];
    const float* fW2=(const float*)d_in[9]; const float* fb2=(const float*)d_in[10];
    const float* g2 =(const float*)d_in[11]; const float* be2=(const float*)d_in[12];
    const float* fW3=(const float*)d_in[13]; const float* fb3=(const float*)d_in[14];
    const float* fW4=(const float*)d_in[15]; const float* fb4=(const float*)d_in[16];
    const float* yW1=(const float*)d_in[17]; const float* yb1=(const float*)d_in[18];
    const float* yW2=(const float*)d_in[19]; const float* yb2=(const float*)d_in[20];
    const float* zW1=(const float*)d_in[21]; const float* zb1=(const float*)d_in[22];
    const float* zW2=(const float*)d_in[23]; const float* zb2=(const float*)d_in[24];
    const float* sg =(const float*)d_in[25]; const float* sb =(const float*)d_in[26];
    float* out = (float*)d_out;

    float *p_z, *p_Dp, *p_bt, *p_fbT, *p_zero, *p_C;
    __half *p_A, *p_B;
    cudaGetSymbolAddress((void**)&p_z,    g_z);
    cudaGetSymbolAddress((void**)&p_Dp,   g_Dp);
    cudaGetSymbolAddress((void**)&p_bt,   g_bt);
    cudaGetSymbolAddress((void**)&p_fbT,  g_fb4T);
    cudaGetSymbolAddress((void**)&p_zero, g_zero);
    cudaGetSymbolAddress((void**)&p_C,    g_C);
    cudaGetSymbolAddress((void**)&p_A,    g_Asp);
    cudaGetSymbolAddress((void**)&p_B,    g_Bsp);

    const int DSM = 98432;
    cudaFuncSetAttribute(k_tc, cudaFuncAttributeMaxDynamicSharedMemorySize, DSM);
    const int SIG_DSM = 64*232*4;
    cudaFuncSetAttribute(k_sig, cudaFuncAttributeMaxDynamicSharedMemorySize, SIG_DSM);

    // prep — k_tc(chunk 0) is the 4th launch (ncu profiles it)
    k_sig    <<<128, 256, SIG_DSM>>>(x, sg, sb);
    k_spline <<<232, 128>>>();
    k_pack   <<<65536 + 16128, 256>>>(fW4);
    k_tc     <<<dim3(CH_ROWS/128, 512), 256, DSM>>>(p_A, p_B, p_C);
    k_packfbT<<<256, 256>>>(fb4);
    k_gemm   <<<dim3(4,1008), 256>>>(p_Dp, p_fbT, p_zero, p_bt, 256, 256);
    k_h0     <<<128, 256>>>(x, hW1, hb1, hW2, hb2);

    // strictly sequential: scan(c) then k_tc(c+1) — no co-residency contention
    for (int c = 0; c < 9; c++){
        if (c >= 1)
            k_tc<<<dim3(CH_ROWS/128, 512), 256, DSM>>>(
                p_A + (size_t)c*CH_ROWS*704, p_B, p_C);
        k_scan<<<64, 512>>>(fW1, fb1, g1, be1, fW2, fb2, g2, be2,
                            fW3, fb3, p_C, p_bt, p_z, c*CH_ROWS);
    }
    k_head<<<128, 256>>>(yW1, yb1, yW2, yb2, zW1, zb1, zW2, zb2, out);
}

// round 17
// speedup vs baseline: 1.5965x; 1.5965x over previous
#include <cuda_runtime.h>
#include <cuda_fp16.h>
#include <cstdint>

#define HSTEP (1.0f/63.0f)
#define CH_STEPS 7
#define CH_ROWS  1792

// ---------------- scratch ----------------
static __device__ float g_y[128*64*232];
static __device__ float g_dknot[63*232*128];
static __device__ float g_dmid [63*232*128];
static __device__ float g_z[128*256];
// precompute path (fp16 3-segment split)
static __device__ __half g_Asp[(size_t)16128*704];   // [Dh|Dh|Dl]
static __device__ __half g_Bsp[(size_t)65536*704];   // [Bh|Bl|Bh]
static __device__ float g_Dp [(size_t)16128*256];
static __device__ float g_bt [(size_t)16128*256];
static __device__ float g_fb4T[256*256];
static __device__ float g_zero[256];
static __device__ float g_C[(size_t)2*CH_ROWS*65536];   // two 470 MB ring halves

// ---------------- helpers ----------------
__device__ __forceinline__ float2 ffma2(float2 a, float2 b, float2 c){
    unsigned long long au, bu, cu, du;
    au = *reinterpret_cast<unsigned long long*>(&a);
    bu = *reinterpret_cast<unsigned long long*>(&b);
    cu = *reinterpret_cast<unsigned long long*>(&c);
    asm("fma.rn.f32x2 %0,%1,%2,%3;" : "=l"(du) : "l"(au), "l"(bu), "l"(cu));
    return *reinterpret_cast<float2*>(&du);
}

__device__ __forceinline__ uint32_t smem_u32(const void* p){
    uint32_t a;
    asm("{ .reg .u64 t; cvta.to.shared.u64 t, %1; cvt.u32.u64 %0, t; }"
        : "=r"(a) : "l"(p));
    return a;
}

__device__ __forceinline__ void ldsm4(uint32_t* r, uint32_t addr){
    asm volatile("ldmatrix.sync.aligned.m8n8.x4.shared.b16 {%0,%1,%2,%3}, [%4];"
        : "=r"(r[0]), "=r"(r[1]), "=r"(r[2]), "=r"(r[3]) : "r"(addr));
}

__device__ __forceinline__ void mma_f16(float* c, const uint32_t* a, const uint32_t* b){
    asm volatile("mma.sync.aligned.m16n8k16.row.col.f32.f16.f16.f32 "
        "{%0,%1,%2,%3}, {%4,%5,%6,%7}, {%8,%9}, {%0,%1,%2,%3};"
        : "+f"(c[0]), "+f"(c[1]), "+f"(c[2]), "+f"(c[3])
        : "r"(a[0]), "r"(a[1]), "r"(a[2]), "r"(a[3]), "r"(b[0]), "r"(b[1]));
}

__device__ __forceinline__ void cpasync16(uint32_t dst, const void* src){
    asm volatile("cp.async.cg.shared.global [%0], [%1], 16;" :: "r"(dst), "l"(src));
}

__device__ __forceinline__ void block_reduce_sum4(float& s0, float& q0,
                                                  float& s1, float& q1){
    __shared__ float sh[128];
    const unsigned m = 0xffffffffu;
    #pragma unroll
    for (int off = 16; off; off >>= 1){
        s0 += __shfl_down_sync(m, s0, off);
        q0 += __shfl_down_sync(m, q0, off);
        s1 += __shfl_down_sync(m, s1, off);
        q1 += __shfl_down_sync(m, q1, off);
    }
    int w = threadIdx.x >> 5, l = threadIdx.x & 31;
    if (l == 0){ sh[w] = s0; sh[32+w] = q0; sh[64+w] = s1; sh[96+w] = q1; }
    __syncthreads();
    if (threadIdx.x == 0){
        float a = 0.f, bq = 0.f, c = 0.f, d = 0.f;
        int nw = blockDim.x >> 5;
        for (int i = 0; i < nw; i++){
            a += sh[i]; bq += sh[32+i]; c += sh[64+i]; d += sh[96+i];
        }
        sh[0] = a; sh[32] = bq; sh[64] = c; sh[96] = d;
    }
    __syncthreads();
    s0 = sh[0]; q0 = sh[32]; s1 = sh[64]; q1 = sh[96];
}

// ---- 1) fused: depth-2 log-signature + sig_norm LN + control y ----
__global__ void k_sig(const float* __restrict__ x,
                      const float* __restrict__ sg, const float* __restrict__ sb){
    extern __shared__ float ls[];
    __shared__ float psh[64*21];
    int b = blockIdx.x, t = threadIdx.x;
    for (int idx = t; idx < 64*21; idx += 256){
        int n = idx / 21, i = idx % 21;
        psh[idx] = (i == 0) ? (float)n * HSTEP : x[(b*64 + n)*20 + (i-1)];
    }
    __syncthreads();
    int ch = t;
    if (ch < 21){
        for (int n = 0; n < 64; n++) ls[n*232 + ch] = psh[n*21 + ch];
    } else if (ch < 231){
        int pp = ch - 21, i = 0, rem = pp;
        while (rem >= 20 - i){ rem -= 20 - i; i++; }
        int j = i + 1 + rem;
        float acc = 0.f, pip = 0.f, pjp = 0.f;
        for (int n = 0; n < 64; n++){
            float pi = psh[n*21 + i], pj = psh[n*21 + j];
            acc += 0.5f*(pip*(pj - pjp) - (pi - pip)*pjp);
            ls[n*232 + ch] = acc;
            pip = pi; pjp = pj;
        }
    }
    __syncthreads();
    int w = t >> 5, l = t & 31;
    const unsigned fm = 0xffffffffu;
    for (int n = w; n < 64; n += 8){
        float s = 0.f, q = 0.f;
        for (int c = l; c < 231; c += 32){
            float v = ls[n*232 + c]; s += v; q += v*v;
        }
        #pragma unroll
        for (int off = 16; off; off >>= 1){
            s += __shfl_down_sync(fm, s, off);
            q += __shfl_down_sync(fm, q, off);
        }
        s = __shfl_sync(fm, s, 0); q = __shfl_sync(fm, q, 0);
        float mean = s*(1.0f/231.0f);
        float var  = q*(1.0f/231.0f) - mean*mean;
        float rstd = rsqrtf(var + 1e-5f);
        size_t ro = ((size_t)b*64 + n)*232;
        for (int c = l; c < 231; c += 32)
            g_y[ro + 1 + c] = (ls[n*232 + c] - mean)*rstd*sg[c] + sb[c];
        if (l == 0) g_y[ro] = (float)n * HSTEP;
    }
}

// ---- 2) natural cubic spline derivatives ----
__global__ void k_spline(){
    __shared__ float cpS[64], idS[64];
    int t = threadIdx.x;
    if (t == 0){
        double ad = (1.0/63.0)/6.0, bd = 2.0*(1.0/63.0)/3.0, cprev = 0.0;
        for (int i = 1; i <= 62; i++){
            double den = bd - ad*cprev, cp = ad/den;
            cpS[i] = (float)cp; idS[i] = (float)(1.0/den); cprev = cp;
        }
    }
    __syncthreads();
    int g = blockIdx.x*128 + t;
    int b = g / 232, c = g % 232;
    float yv[64], M[64];
    for (int n = 0; n < 64; n++) yv[n] = g_y[((size_t)b*64 + n)*232 + c];
    const float ad = HSTEP/6.0f;
    M[0] = 0.f; M[63] = 0.f;
    float prev = 0.f;
    for (int i = 1; i <= 62; i++){
        float rhs = (yv[i+1] - 2.f*yv[i] + yv[i-1]) * 63.0f;
        prev = (rhs - ad*prev) * idS[i];
        M[i] = prev;
    }
    for (int i = 61; i >= 1; i--) M[i] -= cpS[i]*M[i+1];
    for (int n = 0; n < 63; n++){
        float dy = (yv[n+1] - yv[n]) * 63.0f;
        size_t o = ((size_t)n*232 + c)*128 + b;
        g_dknot[o] = dy - (HSTEP/6.0f) *(2.f*M[n] + M[n+1]);
        g_dmid [o] = dy + (HSTEP/24.0f)*(M[n] - M[n+1]);
    }
}

// ---- 3) merged pack: fp16 hi/lo split of fW4 and D ----
__global__ void k_pack(const float* __restrict__ fW4){
    int blk = blockIdx.x, c = threadIdx.x;
    if (blk < 65536){
        if (c < 232){
            float v = fW4[(size_t)blk*232 + c];
            __half h = __float2half(v);
            __half l = __float2half(v - __half2float(h));
            g_Bsp[(size_t)blk*704 + c]       = h;
            g_Bsp[(size_t)blk*704 + 232 + c] = l;
            g_Bsp[(size_t)blk*704 + 464 + c] = h;
        } else if (c < 240){
            g_Bsp[(size_t)blk*704 + 696 + (c - 232)] = __float2half(0.f);
        }
    } else {
        int j = blk - 65536;
        int n = j >> 8, e = (j >> 7) & 1, b = j & 127;
        const float* src = e ? g_dmid : g_dknot;
        if (c < 232){
            float v = src[((size_t)n*232 + c)*128 + b];
            __half h = __float2half(v);
            __half l = __float2half(v - __half2float(h));
            g_Asp[(size_t)j*704 + c]       = h;
            g_Asp[(size_t)j*704 + 232 + c] = h;
            g_Asp[(size_t)j*704 + 464 + c] = l;
            g_Dp[(size_t)j*256 + c] = v;
        } else {
            if (c < 240) g_Asp[(size_t)j*704 + 696 + (c - 232)] = __float2half(0.f);
            g_Dp[(size_t)j*256 + c] = 0.f;
        }
    }
}

__global__ void k_packfbT(const float* __restrict__ fb4){
    int c = blockIdx.x, h = threadIdx.x;
    g_fb4T[c*256 + h] = (c < 232) ? fb4[(size_t)h*232 + c] : 0.f;
}

// ---- 4) initial hidden state ----
__global__ void k_h0(const float* __restrict__ x,  const float* __restrict__ hW1,
                     const float* __restrict__ hb1, const float* __restrict__ hW2,
                     const float* __restrict__ hb2){
    int b = blockIdx.x, t = threadIdx.x;
    __shared__ float x0[20];
    __shared__ float hid[256];
    if (t < 20) x0[t] = x[(size_t)b*64*20 + t];
    __syncthreads();
    float s = hb1[t];
    for (int d = 0; d < 20; d++) s = fmaf(x0[d], hW1[d*256 + t], s);
    hid[t] = fmaxf(s, 0.f);
    __syncthreads();
    float s2 = hb2[t];
    for (int k = 0; k < 256; k++) s2 = fmaf(hid[k], hW2[k*256 + t], s2);
    g_z[b*256 + t] = s2;
}

// ---- generic tiled GEMM (bias-term precompute only) ----
__global__ void __launch_bounds__(256) k_gemm(
    const float* __restrict__ in, const float* __restrict__ W,
    const float* __restrict__ bias, float* __restrict__ out,
    int K, int Nout)
{
    __shared__ float wsh[2048];
    __shared__ float ish[512];
    int n0 = blockIdx.x*64, b0 = blockIdx.y*16;
    int t = threadIdx.x, bi = t >> 4, ng = t & 15;
    float4 bia = *(const float4*)(bias + n0 + ng*4);
    float2 acc0 = make_float2(bia.x, bia.y);
    float2 acc1 = make_float2(bia.z, bia.w);
    for (int k0 = 0; k0 < K; k0 += 32){
        __syncthreads();
        #pragma unroll
        for (int j = 0; j < 8; j++){
            int e = t + j*256;
            wsh[e] = W[(size_t)(k0 + (e >> 6))*Nout + n0 + (e & 63)];
        }
        #pragma unroll
        for (int j = 0; j < 2; j++){
            int e = t + j*256;
            ish[e] = in[(size_t)(b0 + (e >> 5))*K + k0 + (e & 31)];
        }
        __syncthreads();
        #pragma unroll
        for (int kk = 0; kk < 32; kk++){
            float zv = ish[bi*32 + kk];
            float2 zz = make_float2(zv, zv);
            const float2* wp = (const float2*)(wsh + kk*64 + ng*4);
            acc0 = ffma2(zz, wp[0], acc0);
            acc1 = ffma2(zz, wp[1], acc1);
        }
    }
    float4 o = make_float4(acc0.x, acc0.y, acc1.x, acc1.y);
    *(float4*)(out + (size_t)(b0 + bi)*Nout + n0 + ng*4) = o;
}

// ---- big GEMM on fp16 HMMA: C[1792 x 65536] = Asp_chunk @ Bspᵀ, K=704 ----
__global__ void __launch_bounds__(256, 2) k_tc(
    const __half* __restrict__ A, const __half* __restrict__ Bm,
    float* __restrict__ C)
{
    extern __shared__ __align__(128) char dsm[];
    uint32_t base = (smem_u32(dsm) + 127u) & ~127u;
    int t = threadIdx.x, lane = t & 31, warp = t >> 5;
    int mw = warp & 1, nw = warp >> 1;
    size_t j0 = (size_t)blockIdx.x * 128, n0 = (size_t)blockIdx.y * 128;
    const char* Ab = (const char*)A  + j0*1408;
    const char* Bb = (const char*)Bm + n0*1408;

    auto stg = [&](int ck, int s){
        uint32_t sb = base + s*32768u;
        #pragma unroll
        for (int i = 0; i < 4; i++){
            int e = t*4 + i;
            int row = e >> 3, q = e & 7;
            uint32_t d = sb + row*128 + ((q ^ (row & 7)) << 4);
            cpasync16(d, Ab + (size_t)row*1408 + ck*128 + q*16);
        }
        #pragma unroll
        for (int i = 0; i < 4; i++){
            int e = t*4 + i;
            int row = e >> 3, q = e & 7;
            uint32_t d = sb + 16384u + row*128 + ((q ^ (row & 7)) << 4);
            cpasync16(d, Bb + (size_t)row*1408 + ck*128 + q*16);
        }
        asm volatile("cp.async.commit_group;" ::: "memory");
    };

    float acc[4][4][4];
    #pragma unroll
    for (int mi = 0; mi < 4; mi++)
        #pragma unroll
        for (int ni = 0; ni < 4; ni++)
            #pragma unroll
            for (int r = 0; r < 4; r++) acc[mi][ni][r] = 0.f;

    stg(0, 0); stg(1, 1); stg(2, 2);

    for (int ck = 0; ck < 11; ck++){
        if (ck < 8) asm volatile("cp.async.wait_group 2;" ::: "memory");
        else        asm volatile("cp.async.wait_group 0;" ::: "memory");
        __syncthreads();
        uint32_t sA = base + (uint32_t)(ck % 3)*32768u;
        uint32_t sB = sA + 16384u;
        #pragma unroll
        for (int kk = 0; kk < 4; kk++){
            uint32_t afr[4][4], bfr[2][4];
            #pragma unroll
            for (int mi = 0; mi < 4; mi++){
                int row = mw*64 + mi*16 + (lane & 15);
                int q = kk*2 + (lane >> 4);
                ldsm4(afr[mi], sA + row*128 + ((q ^ (row & 7)) << 4));
            }
            #pragma unroll
            for (int nj = 0; nj < 2; nj++){
                int row = nw*32 + nj*16 + (lane & 7) + ((lane >> 4) & 1)*8;
                int q = kk*2 + ((lane >> 3) & 1);
                ldsm4(bfr[nj], sB + row*128 + ((q ^ (row & 7)) << 4));
            }
            #pragma unroll
            for (int mi = 0; mi < 4; mi++)
                #pragma unroll
                for (int ni = 0; ni < 4; ni++)
                    mma_f16(acc[mi][ni], afr[mi], &bfr[ni >> 1][(ni & 1)*2]);
        }
        __syncthreads();
        if (ck + 3 < 11) stg(ck + 3, ck % 3);
    }

    #pragma unroll
    for (int mi = 0; mi < 4; mi++){
        size_t r0 = j0 + mw*64 + mi*16 + (lane >> 2);
        float* row0 = C + r0*65536 + n0 + nw*32 + (lane & 3)*2;
        float* row1 = row0 + (size_t)8*65536;
        #pragma unroll
        for (int ni = 0; ni < 4; ni++){
            *(float2*)(row0 + ni*8) = make_float2(acc[mi][ni][0], acc[mi][ni][1]);
            *(float2*)(row1 + ni*8) = make_float2(acc[mi][ni][2], acc[mi][ni][3]);
        }
    }
}

// ---- persistent scan: 64 blocks x 512 threads, 2 batches per block ----
__global__ void __launch_bounds__(512) k_scan(
    const float* __restrict__ fW1, const float* __restrict__ fb1,
    const float* __restrict__ g1,  const float* __restrict__ be1,
    const float* __restrict__ fW2, const float* __restrict__ fb2,
    const float* __restrict__ g2,  const float* __restrict__ be2,
    const float* __restrict__ fW3, const float* __restrict__ fb3,
    const float* __restrict__ C,   const float* __restrict__ bt,
    float* __restrict__ zg, int jgbase)
{
    int t = threadIdx.x;
    int team = t >> 8, tl = t & 255;
    int bb = blockIdx.x*2;
    __shared__ float zsh[2][256], zmd[2][256];
    __shared__ __align__(16) float a1sh[2][1024];
    __shared__ float a2sh[2][256], a3sh[2][256];
    __shared__ float2 red2[2][2][256];
    __shared__ short lidx[2][256];
    __shared__ int wbase[2][9];

    zsh[team][tl] = zg[(bb + team)*256 + tl];
    __syncthreads();

    for (int s = 0; s < CH_STEPS; s++){
        #pragma unroll
        for (int e = 0; e < 2; e++){
            const float* zin0 = e ? zmd[0] : zsh[0];
            const float* zin1 = e ? zmd[1] : zsh[1];
            // GEMM1 (dense, unroll 16)
            float2 bv = __ldg((const float2*)fb1 + t);
            float2 A0 = bv, A1 = bv;
            #pragma unroll 16
            for (int k = 0; k < 256; k++){
                float2 w = __ldg((const float2*)(fW1 + (size_t)k*1024) + t);
                float z0 = zin0[k], z1 = zin1[k];
                A0 = ffma2(make_float2(z0, z0), w, A0);
                A1 = ffma2(make_float2(z1, z1), w, A1);
            }
            float s0 = A0.x + A0.y, q0 = A0.x*A0.x + A0.y*A0.y;
            float s1 = A1.x + A1.y, q1 = A1.x*A1.x + A1.y*A1.y;
            block_reduce_sum4(s0, q0, s1, q1);
            float m0 = s0*(1.0f/1024.0f), v0 = q0*(1.0f/1024.0f) - m0*m0;
            float m1 = s1*(1.0f/1024.0f), v1 = q1*(1.0f/1024.0f) - m1*m1;
            float r0 = rsqrtf(v0 + 1e-5f), r1 = rsqrtf(v1 + 1e-5f);
            {
                float2 gg = __ldg((const float2*)g1 + t);
                float2 bbv = __ldg((const float2*)be1 + t);
                ((float2*)a1sh[0])[t] = make_float2(
                    fmaxf((A0.x - m0)*r0*gg.x + bbv.x, 0.f),
                    fmaxf((A0.y - m0)*r0*gg.y + bbv.y, 0.f));
                ((float2*)a1sh[1])[t] = make_float2(
                    fmaxf((A1.x - m1)*r1*gg.x + bbv.x, 0.f),
                    fmaxf((A1.y - m1)*r1*gg.y + bbv.y, 0.f));
            }
            __syncthreads();
            // GEMM2 split-k (dense, unroll 16)
            {
                float acc0 = 0.f, acc1 = 0.f;
                const float* wb = fW2 + (size_t)team*512*256 + tl;
                const float* x0 = a1sh[0] + team*512;
                const float* x1 = a1sh[1] + team*512;
                #pragma unroll 16
                for (int k = 0; k < 512; k++){
                    float w = __ldg(wb + (size_t)k*256);
                    acc0 = fmaf(x0[k], w, acc0);
                    acc1 = fmaf(x1[k], w, acc1);
                }
                red2[team][0][tl] = make_float2(acc0, 0.f);
                red2[team][1][tl] = make_float2(acc1, 0.f);
            }
            __syncthreads();
            {
                float tot = red2[0][team][tl].x + red2[1][team][tl].x
                          + __ldg(fb2 + tl);
                float sA = (team == 0) ? tot : 0.f;
                float qA = (team == 0) ? tot*tot : 0.f;
                float sB = (team == 1) ? tot : 0.f;
                float qB = (team == 1) ? tot*tot : 0.f;
                block_reduce_sum4(sA, qA, sB, qB);
                float sm = team ? sB : sA, qm = team ? qB : qA;
                float mean = sm*(1.0f/256.0f), var = qm*(1.0f/256.0f) - mean*mean;
                float rstd = rsqrtf(var + 1e-5f);
                a2sh[team][tl] = fmaxf((tot - mean)*rstd*__ldg(g2 + tl)
                                       + __ldg(be2 + tl), 0.f);
            }
            __syncthreads();
            // GEMM3 (dense, unroll 16)
            float a3v;
            {
                float acc3 = __ldg(fb3 + tl);
                const float* a2p = a2sh[team];
                #pragma unroll 16
                for (int k = 0; k < 256; k++)
                    acc3 = fmaf(a2p[k], __ldg(fW3 + (size_t)k*256 + tl), acc3);
                a3v = fmaxf(acc3, 0.f);
                a3sh[team][tl] = a3v;
            }
            // deterministic ballot-compact nonzero a3 indices (per team)
            {
                int lane = tl & 31, wrp = tl >> 5;
                unsigned ball = __ballot_sync(0xffffffffu, a3v != 0.f);
                if (lane == 0) wbase[team][wrp + 1] = __popc(ball);
                __syncthreads();
                if (tl == 0){
                    int acc = 0;
                    #pragma unroll
                    for (int i = 0; i < 8; i++){
                        int c2 = wbase[team][i + 1];
                        wbase[team][i + 1] = acc; acc += c2;
                    }
                    wbase[team][0] = acc;   // total count
                }
                __syncthreads();
                if (a3v != 0.f){
                    int pos = wbase[team][wrp + 1]
                            + __popc(ball & ((1u << (tl & 31)) - 1u));
                    lidx[team][pos] = (short)tl;
                }
            }
            __syncthreads();
            // sparse C dot (8-wide batched loads) + z update
            {
                int rloc = (2*s + e)*128 + bb + team;
                const float* Crow = C + (size_t)rloc*65536 + tl;
                float g = __ldg(bt + (size_t)(jgbase + rloc)*256 + tl);
                const float* a3p = a3sh[team];
                int n3 = wbase[team][0];
                int k = 0;
                for (; k + 8 <= n3; k += 8){
                    int id[8]; float v[8];
                    #pragma unroll
                    for (int u = 0; u < 8; u++) id[u] = lidx[team][k + u];
                    #pragma unroll
                    for (int u = 0; u < 8; u++)
                        v[u] = __ldg(Crow + (size_t)id[u]*256);
                    #pragma unroll
                    for (int u = 0; u < 8; u++)
                        g = fmaf(a3p[id[u]], v[u], g);
                }
                for (; k < n3; k++){
                    int id = lidx[team][k];
                    g = fmaf(a3p[id], __ldg(Crow + (size_t)id*256), g);
                }
                if (e == 0) zmd[team][tl] = zsh[team][tl] + 0.5f*HSTEP*g;
                else        zsh[team][tl] = zsh[team][tl] + HSTEP*g;
            }
            __syncthreads();
        }
    }
    zg[(bb + team)*256 + tl] = zsh[team][tl];
}

// ---- output heads ----
__global__ void k_head(const float* __restrict__ yW1, const float* __restrict__ yb1,
                       const float* __restrict__ yW2, const float* __restrict__ yb2,
                       const float* __restrict__ zW1, const float* __restrict__ zb1,
                       const float* __restrict__ zW2, const float* __restrict__ zb2,
                       float* __restrict__ out){
    int b = blockIdx.x, t = threadIdx.x;
    __shared__ float hsh[256], t1[128], t2[256];
    hsh[t] = g_z[b*256 + t];
    __syncthreads();
    float s = zb1[t];
    for (int k = 0; k < 256; k++) s = fmaf(hsh[k], zW1[k*256 + t], s);
    t2[t] = fmaxf(s, 0.f);
    if (t < 128){
        float s1 = yb1[t];
        for (int k = 0; k < 256; k++) s1 = fmaf(hsh[k], yW1[k*128 + t], s1);
        t1[t] = fmaxf(s1, 0.f);
    }
    __syncthreads();
    if (t == 0){
        float y = yb2[0];
        for (int j = 0; j < 128; j++) y = fmaf(t1[j], yW2[j], y);
        out[b] = y;
    }
    if (t < 20){
        float zz = zb2[t];
        for (int k = 0; k < 256; k++) zz = fmaf(t2[k], zW2[k*20 + t], zz);
        out[128 + b*20 + t] = zz;
    }
    out[128 + 2560 + b*256 + t] = hsh[t];
}

extern "C" void kernel_launch(void* const* d_in, const int* in_sizes, int n_in,
                              void* d_out, int out_size){
    const float* x  =(const float*)d_in[0];
    const float* hW1=(const float*)d_in[1]; const float* hb1=(const float*)d_in[2];
    const float* hW2=(const float*)d_in[3]; const float* hb2=(const float*)d_in[4];
    const float* fW1=(const float*)d_in[5]; const float* fb1=(const float*)d_in[6];
    const float* g1 =(const float*)d_in[7]; const float* be1=(const float*)d_in[8];
    const float* fW2=(const float*)d_in[9]; const float* fb2=(const float*)d_in[10];
    const float* g2 =(const float*)d_in[11]; const float* be2=(const float*)d_in[12];
    const float* fW3=(const float*)d_in[13]; const float* fb3=(const float*)d_in[14];
    const float* fW4=(const float*)d_in[15]; const float* fb4=(const float*)d_in[16];
    const float* yW1=(const float*)d_in[17]; const float* yb1=(const float*)d_in[18];
    const float* yW2=(const float*)d_in[19]; const float* yb2=(const float*)d_in[20];
    const float* zW1=(const float*)d_in[21]; const float* zb1=(const float*)d_in[22];
    const float* zW2=(const float*)d_in[23]; const float* zb2=(const float*)d_in[24];
    const float* sg =(const float*)d_in[25]; const float* sb =(const float*)d_in[26];
    float* out = (float*)d_out;

    float *p_z, *p_Dp, *p_bt, *p_fbT, *p_zero, *p_C;
    __half *p_A, *p_B;
    cudaGetSymbolAddress((void**)&p_z,    g_z);
    cudaGetSymbolAddress((void**)&p_Dp,   g_Dp);
    cudaGetSymbolAddress((void**)&p_bt,   g_bt);
    cudaGetSymbolAddress((void**)&p_fbT,  g_fb4T);
    cudaGetSymbolAddress((void**)&p_zero, g_zero);
    cudaGetSymbolAddress((void**)&p_C,    g_C);
    cudaGetSymbolAddress((void**)&p_A,    g_Asp);
    cudaGetSymbolAddress((void**)&p_B,    g_Bsp);

    static cudaStream_t s2 = nullptr;
    static cudaEvent_t ePrep, eT[9], eS[9];
    if (!s2){
        int loPri, hiPri;
        cudaDeviceGetStreamPriorityRange(&loPri, &hiPri);
        cudaStreamCreateWithPriority(&s2, cudaStreamNonBlocking, loPri);
        cudaEventCreateWithFlags(&ePrep, cudaEventDisableTiming);
        for (int i = 0; i < 9; i++){
            cudaEventCreateWithFlags(&eT[i], cudaEventDisableTiming);
            cudaEventCreateWithFlags(&eS[i], cudaEventDisableTiming);
        }
    }

    const int DSM = 98432;
    cudaFuncSetAttribute(k_tc, cudaFuncAttributeMaxDynamicSharedMemorySize, DSM);
    const int SIG_DSM = 64*232*4;
    cudaFuncSetAttribute(k_sig, cudaFuncAttributeMaxDynamicSharedMemorySize, SIG_DSM);

    const size_t CHALF = (size_t)CH_ROWS*65536;

    // prep
    k_sig    <<<128, 256, SIG_DSM>>>(x, sg, sb);
    k_spline <<<232, 128>>>();
    k_pack   <<<65536 + 16128, 256>>>(fW4);
    cudaEventRecord(ePrep, 0);
    k_tc     <<<dim3(CH_ROWS/128, 512), 256, DSM>>>(p_A, p_B, p_C);
    cudaEventRecord(eT[0], 0);
    k_packfbT<<<256, 256>>>(fb4);
    k_gemm   <<<dim3(4,1008), 256>>>(p_Dp, p_fbT, p_zero, p_bt, 256, 256);
    k_h0     <<<128, 256>>>(x, hW1, hb1, hW2, hb2);

    cudaStreamWaitEvent(s2, ePrep, 0);

    for (int c = 0; c < 9; c++){
        if (c >= 1){
            if (c >= 2) cudaStreamWaitEvent(s2, eS[c-2], 0);
            k_tc<<<dim3(CH_ROWS/128, 512), 256, DSM, s2>>>(
                p_A + (size_t)c*CH_ROWS*704, p_B, p_C + (size_t)(c & 1)*CHALF);
            cudaEventRecord(eT[c], s2);
            cudaStreamWaitEvent(0, eT[c], 0);
        }
        k_scan<<<64, 512>>>(fW1, fb1, g1, be1, fW2, fb2, g2, be2,
                            fW3, fb3, p_C + (size_t)(c & 1)*CHALF, p_bt,
                            p_z, c*CH_ROWS);
        cudaEventRecord(eS[c], 0);
    }
    k_head<<<128, 256>>>(yW1, yb1, yW2, yb2, zW1, zb1, zW2, zb2, out);
}